// round 13
// baseline (speedup 1.0000x reference)
#include <cuda_runtime.h>
#include <cuda_fp16.h>
#include <math.h>
#include <stdint.h>

// Problem constants
#define BB    4
#define NQ    2048
#define NKV   4096
#define QDIM  512
#define KVDIM 128
#define NH    8
#define HD    64
#define INNER 512
// attention scale folded with log2(e): 0.125 * 1.4426950408889634
#define Q_PRESCALE 0.18033688011112042f

// ---------------------------------------------------------------------------
// Scratch. Q/K half [b][tok][h*64+d]; V half TRANSPOSED [b][h][d][key];
// AO half (feeds fp16 O-projection). All GEMM inputs pre-rounded to half.
// ---------------------------------------------------------------------------
__device__ __half g_Qh [BB * NQ  * INNER];
__device__ __half g_Kh [BB * NKV * INNER];
__device__ __half g_Vh [BB * NKV * INNER];
__device__ __half g_AOh[BB * NQ  * INNER];
__device__ __half g_Rq [BB * NQ  * QDIM];
__device__ __half g_Rkv[BB * NKV * KVDIM];
__device__ __half g_Rwq[INNER * QDIM];
__device__ __half g_Rwk[INNER * KVDIM];
__device__ __half g_Rwv[INNER * KVDIM];
__device__ __half g_Rwo[QDIM * INNER];

// ---------------------------------------------------------------------------
// Helpers
// ---------------------------------------------------------------------------
__device__ __forceinline__ uint32_t smem_u32(const void* p) {
    uint32_t a;
    asm("{ .reg .u64 t; cvta.to.shared.u64 t, %1; cvt.u32.u64 %0, t; }"
        : "=r"(a) : "l"(p));
    return a;
}
__device__ __forceinline__ void cp16(uint32_t dst, const void* src) {
    asm volatile("cp.async.cg.shared.global [%0], [%1], 16;\n"
                 :: "r"(dst), "l"(src));
}
#define CP_COMMIT() asm volatile("cp.async.commit_group;\n")
#define CP_WAIT1()  asm volatile("cp.async.wait_group 1;\n")
#define CP_WAIT0()  asm volatile("cp.async.wait_group 0;\n")

__device__ __forceinline__ float ex2(float x) {
    float r;
    asm("ex2.approx.f32 %0, %1;" : "=f"(r) : "f"(x));
    return r;
}
__device__ __forceinline__ uint32_t packh2(float a, float b) {
    __half2 h = __floats2half2_rn(a, b);
    return *(uint32_t*)&h;
}
__device__ __forceinline__ void mma_f16(float d[4], const uint32_t a[4],
                                        const uint32_t b[2], const float c[4]) {
    asm volatile(
        "mma.sync.aligned.m16n8k16.row.col.f32.f16.f16.f32 "
        "{%0,%1,%2,%3}, {%4,%5,%6,%7}, {%8,%9}, {%10,%11,%12,%13};\n"
        : "=f"(d[0]), "=f"(d[1]), "=f"(d[2]), "=f"(d[3])
        : "r"(a[0]), "r"(a[1]), "r"(a[2]), "r"(a[3]),
          "r"(b[0]), "r"(b[1]),
          "f"(c[0]), "f"(c[1]), "f"(c[2]), "f"(c[3]));
}
__device__ __forceinline__ void ldsm4(uint32_t& r0, uint32_t& r1,
                                      uint32_t& r2, uint32_t& r3, uint32_t addr) {
    asm volatile("ldmatrix.sync.aligned.m8n8.x4.shared.b16 {%0,%1,%2,%3}, [%4];\n"
                 : "=r"(r0), "=r"(r1), "=r"(r2), "=r"(r3) : "r"(addr));
}

// ---------------------------------------------------------------------------
// Elementwise fp32 -> fp16 rounding
// ---------------------------------------------------------------------------
__global__ __launch_bounds__(256) void round_f16_kernel(
    const float* __restrict__ in, __half* __restrict__ out, int n4)
{
    int i = blockIdx.x * 256 + threadIdx.x;
    if (i < n4) {
        float4 v = ((const float4*)in)[i];
        __half2 lo = __floats2half2_rn(v.x, v.y);
        __half2 hi = __floats2half2_rn(v.z, v.w);
        uint2 u;
        u.x = *(uint32_t*)&lo; u.y = *(uint32_t*)&hi;
        ((uint2*)out)[i] = u;
    }
}

// ---------------------------------------------------------------------------
// FP16 NT GEMM: C = scale*(A[M,K] @ W[N,K]^T) (+ bias), fp32 accumulate.
// Tile 128x64x64, 128 threads = 4 warps x 32 rows; ldmatrix A and B frags.
// OUT_MODE: 0 = fp32, 2 = half, 3 = half scattered V^T [b][h][d][key]
// ---------------------------------------------------------------------------
#define GSTR 72
#define GEMM_SMEM ((2*128*GSTR + 2*64*GSTR) * 2)

template <bool HAS_BIAS, int OUT_MODE>
__global__ __launch_bounds__(128) void gemm_f16_kernel(
    const __half* __restrict__ A, const __half* __restrict__ W,
    const float* __restrict__ bias, void* __restrict__ Cv,
    int M, int N, int K, float scale)
{
    extern __shared__ __half gsh[];
    __half* sA = gsh;                    // [2][128][72]
    __half* sW = gsh + 2*128*GSTR;       // [2][64][72]
    const uint32_t sA_u = smem_u32(sA);
    const uint32_t sW_u = smem_u32(sW);

    const int tid = threadIdx.x;
    const int lane = tid & 31, w = tid >> 5;
    const int g = lane >> 2, t = lane & 3;
    const int bm = blockIdx.y * 128, bn = blockIdx.x * 64;
    const int NIT = K / 64;

    const int arow = (lane & 15), acol = (lane >> 4)*8;
    const int brow = ((lane >> 4)*8 + (lane & 7));
    const int bcol = ((lane >> 3) & 1)*8;

    float acc[2][8][4];
#pragma unroll
    for (int r = 0; r < 2; r++)
#pragma unroll
        for (int nb = 0; nb < 8; nb++)
#pragma unroll
            for (int j = 0; j < 4; j++) acc[r][nb][j] = 0.f;

    {
#pragma unroll
        for (int i = 0; i < 8; i++) {
            int idx = tid + i*128, row = idx >> 3, c = idx & 7;
            cp16(sA_u + (row*GSTR + c*8)*2, A + (size_t)(bm + row)*K + c*8);
        }
#pragma unroll
        for (int i = 0; i < 4; i++) {
            int idx = tid + i*128, row = idx >> 3, c = idx & 7;
            cp16(sW_u + (row*GSTR + c*8)*2, W + (size_t)(bn + row)*K + c*8);
        }
        CP_COMMIT();
    }

    for (int it = 0; it < NIT; it++) {
        const int buf = it & 1;
        if (it + 1 < NIT) {
            const int k0 = (it + 1) * 64, nbuf = buf ^ 1;
#pragma unroll
            for (int i = 0; i < 8; i++) {
                int idx = tid + i*128, row = idx >> 3, c = idx & 7;
                cp16(sA_u + (nbuf*128*GSTR + row*GSTR + c*8)*2,
                     A + (size_t)(bm + row)*K + k0 + c*8);
            }
#pragma unroll
            for (int i = 0; i < 4; i++) {
                int idx = tid + i*128, row = idx >> 3, c = idx & 7;
                cp16(sW_u + (nbuf*64*GSTR + row*GSTR + c*8)*2,
                     W + (size_t)(bn + row)*K + k0 + c*8);
            }
            CP_COMMIT();
            CP_WAIT1();
        } else {
            CP_WAIT0();
        }
        __syncthreads();

        const uint32_t tA_u = sA_u + buf*128*GSTR*2;
        const uint32_t tW_u = sW_u + buf*64*GSTR*2;

#pragma unroll
        for (int ks = 0; ks < 4; ks++) {
            uint32_t a0[4], a1[4];
            ldsm4(a0[0], a0[1], a0[2], a0[3],
                  tA_u + ((w*32 + arow)*GSTR + ks*16 + acol)*2);
            ldsm4(a1[0], a1[1], a1[2], a1[3],
                  tA_u + ((w*32 + 16 + arow)*GSTR + ks*16 + acol)*2);
#pragma unroll
            for (int p = 0; p < 4; p++) {
                uint32_t b0, b1, b2, b3;
                ldsm4(b0, b1, b2, b3,
                      tW_u + ((p*16 + brow)*GSTR + ks*16 + bcol)*2);
                uint32_t bl[2] = {b0, b1}, bh[2] = {b2, b3};
                mma_f16(acc[0][2*p    ], a0, bl, acc[0][2*p    ]);
                mma_f16(acc[0][2*p + 1], a0, bh, acc[0][2*p + 1]);
                mma_f16(acc[1][2*p    ], a1, bl, acc[1][2*p    ]);
                mma_f16(acc[1][2*p + 1], a1, bh, acc[1][2*p + 1]);
            }
        }
        __syncthreads();
    }

#pragma unroll
    for (int r = 0; r < 2; r++) {
        const int r0 = bm + w*32 + r*16 + g, r1 = r0 + 8;
#pragma unroll
        for (int nb = 0; nb < 8; nb++) {
            const int col = bn + nb*8 + 2*t;
            float v00 = acc[r][nb][0]*scale, v01 = acc[r][nb][1]*scale;
            float v10 = acc[r][nb][2]*scale, v11 = acc[r][nb][3]*scale;
            if (HAS_BIAS) {
                float b0 = bias[col], b1 = bias[col + 1];
                v00 += b0; v01 += b1; v10 += b0; v11 += b1;
            }
            if (OUT_MODE == 0) {
                float* C = (float*)Cv;
                *(float2*)&C[(size_t)r0*N + col] = make_float2(v00, v01);
                *(float2*)&C[(size_t)r1*N + col] = make_float2(v10, v11);
            } else if (OUT_MODE == 2) {
                __half* C = (__half*)Cv;
                *(__half2*)&C[(size_t)r0*N + col] = __floats2half2_rn(v00, v01);
                *(__half2*)&C[(size_t)r1*N + col] = __floats2half2_rn(v10, v11);
            } else {
                __half* C = (__half*)Cv;
                int b_ = r0 >> 12;
                int key0 = r0 & (NKV - 1), key1 = r1 & (NKV - 1);
                size_t base0 = ((size_t)(b_*NH + (col >> 6))*HD + (col & 63)) * NKV;
                size_t base1 = base0 + NKV;
                C[base0 + key0] = __float2half_rn(v00);
                C[base1 + key0] = __float2half_rn(v01);
                C[base0 + key1] = __float2half_rn(v10);
                C[base1 + key1] = __float2half_rn(v11);
            }
        }
    }
}

// ---------------------------------------------------------------------------
// Flash-attention core, fp16 + m16n8k16, fp32 accumulate.
// R13: register-direct P (FA2 trick): for fp16, the S C-fragment layout
// (rows g/g+8, cols 2t/2t+1) IS the PV A-fragment layout, so P never touches
// smem — no P stores, no P ldmatrix, no syncwarp.  P smem gone -> 54KB/CTA,
// 3 CTAs/SM (12 warps) for issue-rate.  P values identical to R11/R12.
// ---------------------------------------------------------------------------
#define BQ    128
#define KT    64
#define STRH  72
#define NITA  (NKV / KT)
#define ATTN_SMEM ((2*KT*STRH + 2*KT*STRH + BQ*STRH) * 2)

__global__ __launch_bounds__(128, 3) void attn_mma_kernel()
{
    extern __shared__ __half smh[];
    __half* sK  = smh;                   // [2][64][72]
    __half* sVt = sK + 2*KT*STRH;        // [2][64][72]
    __half* sQ  = sVt + 2*KT*STRH;       // [128][72]  Q staging only
    const uint32_t sK_u  = smem_u32(sK);
    const uint32_t sVt_u = smem_u32(sVt);
    const uint32_t sQ_u  = smem_u32(sQ);

    const int qt = blockIdx.x, h = blockIdx.y, b = blockIdx.z;
    const int tid = threadIdx.x, lane = tid & 31, w = tid >> 5;
    const int g = lane >> 2, t = lane & 3;

    const __half* Qb  = g_Qh + (size_t)(b*NQ + qt*BQ)*INNER + h*HD;
    const __half* Kb  = g_Kh + (size_t)b*NKV*INNER + h*HD;
    const __half* Vtb = g_Vh + ((size_t)(b*NH + h)*HD)*NKV;

    const int kvrow = ((lane >> 4)*8 + (lane & 7));
    const int kvcol = ((lane >> 3) & 1)*8;

#pragma unroll
    for (int i = 0; i < 8; i++) {
        int idx = tid + i*128, row = idx >> 3, c = idx & 7;
        cp16(sQ_u + (row*STRH + c*8)*2, Qb + (size_t)row*INNER + c*8);
    }
    CP_COMMIT();

#pragma unroll
    for (int i = 0; i < 4; i++) {
        int idx = tid + i*128, row = idx >> 3, c = idx & 7;
        cp16(sK_u  + (row*STRH + c*8)*2, Kb  + (size_t)row*INNER + c*8);
        cp16(sVt_u + (row*STRH + c*8)*2, Vtb + (size_t)row*NKV   + c*8);
    }
    CP_COMMIT();

    CP_WAIT1();
    __syncthreads();

    uint32_t qa[2][4][4];
#pragma unroll
    for (int r = 0; r < 2; r++)
#pragma unroll
        for (int ks = 0; ks < 4; ks++) {
            const int row = w*32 + r*16;
            const int c0 = ks*16 + 2*t;
            qa[r][ks][0] = *(const uint32_t*)&sQ[(row + g    )*STRH + c0];
            qa[r][ks][1] = *(const uint32_t*)&sQ[(row + g + 8)*STRH + c0];
            qa[r][ks][2] = *(const uint32_t*)&sQ[(row + g    )*STRH + c0 + 8];
            qa[r][ks][3] = *(const uint32_t*)&sQ[(row + g + 8)*STRH + c0 + 8];
        }

    float m0[2], m1[2], l0[2], l1[2];
#pragma unroll
    for (int r = 0; r < 2; r++) { m0[r] = m1[r] = -INFINITY; l0[r] = l1[r] = 0.f; }
    float o[2][8][4];
#pragma unroll
    for (int r = 0; r < 2; r++)
#pragma unroll
        for (int db = 0; db < 8; db++)
#pragma unroll
            for (int j = 0; j < 4; j++) o[r][db][j] = 0.f;

    for (int it = 0; it < NITA; it++) {
        const int buf = it & 1;
        if (it + 1 < NITA) {
            const int nbuf = buf ^ 1;
#pragma unroll
            for (int i = 0; i < 4; i++) {
                int idx = tid + i*128, row = idx >> 3, c = idx & 7;
                cp16(sK_u  + (nbuf*KT*STRH + row*STRH + c*8)*2,
                     Kb  + (size_t)((it + 1)*KT + row)*INNER + c*8);
                cp16(sVt_u + (nbuf*KT*STRH + row*STRH + c*8)*2,
                     Vtb + (size_t)row*NKV + (it + 1)*KT + c*8);
            }
            CP_COMMIT();
            CP_WAIT1();
        } else {
            CP_WAIT0();
        }
        __syncthreads();

        const uint32_t tK_u  = sK_u  + buf*KT*STRH*2;
        const uint32_t tVt_u = sVt_u + buf*KT*STRH*2;

        // ---- S = Q K^T ----
        float s[2][8][4];
#pragma unroll
        for (int r = 0; r < 2; r++)
#pragma unroll
            for (int nb = 0; nb < 8; nb++)
#pragma unroll
                for (int j = 0; j < 4; j++) s[r][nb][j] = 0.f;

#pragma unroll
        for (int ks = 0; ks < 4; ks++) {
#pragma unroll
            for (int p = 0; p < 4; p++) {
                uint32_t b0, b1, b2, b3;
                ldsm4(b0, b1, b2, b3,
                      tK_u + ((p*16 + kvrow)*STRH + ks*16 + kvcol)*2);
                uint32_t bl[2] = {b0, b1}, bh[2] = {b2, b3};
                mma_f16(s[0][2*p    ], qa[0][ks], bl, s[0][2*p    ]);
                mma_f16(s[0][2*p + 1], qa[0][ks], bh, s[0][2*p + 1]);
                mma_f16(s[1][2*p    ], qa[1][ks], bl, s[1][2*p    ]);
                mma_f16(s[1][2*p + 1], qa[1][ks], bh, s[1][2*p + 1]);
            }
        }

        // ---- online softmax (exp2 domain); P packed into registers ----
        uint32_t ph[2][8][2];   // [row-block][key-block][row g / g+8] half2
#pragma unroll
        for (int r = 0; r < 2; r++) {
            float rm0 = -INFINITY, rm1 = -INFINITY;
#pragma unroll
            for (int nb = 0; nb < 8; nb++) {
                rm0 = fmaxf(rm0, fmaxf(s[r][nb][0], s[r][nb][1]));
                rm1 = fmaxf(rm1, fmaxf(s[r][nb][2], s[r][nb][3]));
            }
            rm0 = fmaxf(rm0, __shfl_xor_sync(0xffffffffu, rm0, 1));
            rm0 = fmaxf(rm0, __shfl_xor_sync(0xffffffffu, rm0, 2));
            rm1 = fmaxf(rm1, __shfl_xor_sync(0xffffffffu, rm1, 1));
            rm1 = fmaxf(rm1, __shfl_xor_sync(0xffffffffu, rm1, 2));

            float mn0 = fmaxf(m0[r], rm0), mn1 = fmaxf(m1[r], rm1);
            float corr0 = ex2(m0[r] - mn0), corr1 = ex2(m1[r] - mn1);
            m0[r] = mn0; m1[r] = mn1;

            float rs0 = 0.f, rs1 = 0.f;
#pragma unroll
            for (int nb = 0; nb < 8; nb++) {
                float e0 = ex2(s[r][nb][0] - mn0);
                float e1 = ex2(s[r][nb][1] - mn0);
                float e2 = ex2(s[r][nb][2] - mn1);
                float e3 = ex2(s[r][nb][3] - mn1);
                rs0 += e0 + e1;
                rs1 += e2 + e3;
                ph[r][nb][0] = packh2(e0, e1);
                ph[r][nb][1] = packh2(e2, e3);
            }
            rs0 += __shfl_xor_sync(0xffffffffu, rs0, 1);
            rs0 += __shfl_xor_sync(0xffffffffu, rs0, 2);
            rs1 += __shfl_xor_sync(0xffffffffu, rs1, 1);
            rs1 += __shfl_xor_sync(0xffffffffu, rs1, 2);
            l0[r] = l0[r] * corr0 + rs0;
            l1[r] = l1[r] * corr1 + rs1;

#pragma unroll
            for (int db = 0; db < 8; db++) {
                o[r][db][0] *= corr0; o[r][db][1] *= corr0;
                o[r][db][2] *= corr1; o[r][db][3] *= corr1;
            }
        }

        // ---- O += P V : P fragments direct from registers ----
#pragma unroll
        for (int ks = 0; ks < 4; ks++) {
            uint32_t pa0[4] = { ph[0][2*ks][0], ph[0][2*ks][1],
                                ph[0][2*ks+1][0], ph[0][2*ks+1][1] };
            uint32_t pa1[4] = { ph[1][2*ks][0], ph[1][2*ks][1],
                                ph[1][2*ks+1][0], ph[1][2*ks+1][1] };
#pragma unroll
            for (int p = 0; p < 4; p++) {
                uint32_t b0, b1, b2, b3;
                ldsm4(b0, b1, b2, b3,
                      tVt_u + ((p*16 + kvrow)*STRH + ks*16 + kvcol)*2);
                uint32_t bl[2] = {b0, b1}, bh[2] = {b2, b3};
                mma_f16(o[0][2*p    ], pa0, bl, o[0][2*p    ]);
                mma_f16(o[0][2*p + 1], pa0, bh, o[0][2*p + 1]);
                mma_f16(o[1][2*p    ], pa1, bl, o[1][2*p    ]);
                mma_f16(o[1][2*p + 1], pa1, bh, o[1][2*p + 1]);
            }
        }
        __syncthreads();
    }

    // ---- epilogue ----
#pragma unroll
    for (int r = 0; r < 2; r++) {
        const float inv0 = 1.f / l0[r], inv1 = 1.f / l1[r];
        const int q0 = qt*BQ + w*32 + r*16 + g, q1 = q0 + 8;
#pragma unroll
        for (int db = 0; db < 8; db++) {
            *(__half2*)&g_AOh[(size_t)(b*NQ + q0)*INNER + h*HD + db*8 + 2*t] =
                __floats2half2_rn(o[r][db][0]*inv0, o[r][db][1]*inv0);
            *(__half2*)&g_AOh[(size_t)(b*NQ + q1)*INNER + h*HD + db*8 + 2*t] =
                __floats2half2_rn(o[r][db][2]*inv1, o[r][db][3]*inv1);
        }
    }
}

// ---------------------------------------------------------------------------
// Launch
// ---------------------------------------------------------------------------
extern "C" void kernel_launch(void* const* d_in, const int* in_sizes, int n_in,
                              void* d_out, int out_size)
{
    const float* q   = (const float*)d_in[0];
    const float* kv  = (const float*)d_in[1];
    const float* w_q = (const float*)d_in[2];
    const float* w_k = (const float*)d_in[3];
    const float* w_v = (const float*)d_in[4];
    const float* w_o = (const float*)d_in[5];
    const float* b_o = (const float*)d_in[6];
    float* out = (float*)d_out;

    void *Qh, *Kh, *Vh, *AOh, *Rq, *Rkv, *Rwq, *Rwk, *Rwv, *Rwo;
    cudaGetSymbolAddress(&Qh,  g_Qh);
    cudaGetSymbolAddress(&Kh,  g_Kh);
    cudaGetSymbolAddress(&Vh,  g_Vh);
    cudaGetSymbolAddress(&AOh, g_AOh);
    cudaGetSymbolAddress(&Rq,  g_Rq);
    cudaGetSymbolAddress(&Rkv, g_Rkv);
    cudaGetSymbolAddress(&Rwq, g_Rwq);
    cudaGetSymbolAddress(&Rwk, g_Rwk);
    cudaGetSymbolAddress(&Rwv, g_Rwv);
    cudaGetSymbolAddress(&Rwo, g_Rwo);

    const int MQ = BB * NQ;    // 8192
    const int MK = BB * NKV;   // 16384

    cudaFuncSetAttribute(gemm_f16_kernel<false, 2>,
                         cudaFuncAttributeMaxDynamicSharedMemorySize, GEMM_SMEM);
    cudaFuncSetAttribute(gemm_f16_kernel<false, 3>,
                         cudaFuncAttributeMaxDynamicSharedMemorySize, GEMM_SMEM);
    cudaFuncSetAttribute(gemm_f16_kernel<true, 0>,
                         cudaFuncAttributeMaxDynamicSharedMemorySize, GEMM_SMEM);
    cudaFuncSetAttribute(attn_mma_kernel,
                         cudaFuncAttributeMaxDynamicSharedMemorySize, ATTN_SMEM);

    // ---- pre-round GEMM inputs to fp16 ----
    {
        int n;
        n = MQ*QDIM/4;      round_f16_kernel<<<(n+255)/256, 256>>>(q,   (__half*)Rq,  n);
        n = MK*KVDIM/4;     round_f16_kernel<<<(n+255)/256, 256>>>(kv,  (__half*)Rkv, n);
        n = INNER*QDIM/4;   round_f16_kernel<<<(n+255)/256, 256>>>(w_q, (__half*)Rwq, n);
        n = INNER*KVDIM/4;  round_f16_kernel<<<(n+255)/256, 256>>>(w_k, (__half*)Rwk, n);
        n = INNER*KVDIM/4;  round_f16_kernel<<<(n+255)/256, 256>>>(w_v, (__half*)Rwv, n);
        n = QDIM*INNER/4;   round_f16_kernel<<<(n+255)/256, 256>>>(w_o, (__half*)Rwo, n);
    }

    gemm_f16_kernel<false, 2><<<dim3(INNER/64, MQ/128), 128, GEMM_SMEM>>>(
        (__half*)Rq, (__half*)Rwq, nullptr, Qh, MQ, INNER, QDIM, Q_PRESCALE);
    gemm_f16_kernel<false, 2><<<dim3(INNER/64, MK/128), 128, GEMM_SMEM>>>(
        (__half*)Rkv, (__half*)Rwk, nullptr, Kh, MK, INNER, KVDIM, 1.0f);
    gemm_f16_kernel<false, 3><<<dim3(INNER/64, MK/128), 128, GEMM_SMEM>>>(
        (__half*)Rkv, (__half*)Rwv, nullptr, Vh, MK, INNER, KVDIM, 1.0f);

    attn_mma_kernel<<<dim3(NQ/BQ, NH, BB), 128, ATTN_SMEM>>>();

    gemm_f16_kernel<true, 0><<<dim3(QDIM/64, MQ/128), 128, GEMM_SMEM>>>(
        (__half*)AOh, (__half*)Rwo, b_o, out, MQ, QDIM, INNER, 1.0f);
}

// round 15
// speedup vs baseline: 1.2201x; 1.2201x over previous
#include <cuda_runtime.h>
#include <cuda_fp16.h>
#include <math.h>
#include <stdint.h>

// Problem constants
#define BB    4
#define NQ    2048
#define NKV   4096
#define QDIM  512
#define KVDIM 128
#define NH    8
#define HD    64
#define INNER 512
// attention scale folded with log2(e): 0.125 * 1.4426950408889634
#define Q_PRESCALE 0.18033688011112042f

// ---------------------------------------------------------------------------
// Scratch. Q/K half [b][tok][h*64+d]; V half TRANSPOSED [b][h][d][key];
// AO half (feeds fp16 O-projection). All GEMM inputs pre-rounded to half.
// ---------------------------------------------------------------------------
__device__ __half g_Qh [BB * NQ  * INNER];
__device__ __half g_Kh [BB * NKV * INNER];
__device__ __half g_Vh [BB * NKV * INNER];
__device__ __half g_AOh[BB * NQ  * INNER];
__device__ __half g_Rq [BB * NQ  * QDIM];
__device__ __half g_Rkv[BB * NKV * KVDIM];
__device__ __half g_Rwq[INNER * QDIM];
__device__ __half g_Rwk[INNER * KVDIM];
__device__ __half g_Rwv[INNER * KVDIM];
__device__ __half g_Rwo[QDIM * INNER];

// ---------------------------------------------------------------------------
// Helpers
// ---------------------------------------------------------------------------
__device__ __forceinline__ uint32_t smem_u32(const void* p) {
    uint32_t a;
    asm("{ .reg .u64 t; cvta.to.shared.u64 t, %1; cvt.u32.u64 %0, t; }"
        : "=r"(a) : "l"(p));
    return a;
}
__device__ __forceinline__ void cp16(uint32_t dst, const void* src) {
    asm volatile("cp.async.cg.shared.global [%0], [%1], 16;\n"
                 :: "r"(dst), "l"(src));
}
#define CP_COMMIT() asm volatile("cp.async.commit_group;\n")
#define CP_WAIT1()  asm volatile("cp.async.wait_group 1;\n")
#define CP_WAIT0()  asm volatile("cp.async.wait_group 0;\n")

__device__ __forceinline__ float ex2(float x) {
    float r;
    asm("ex2.approx.f32 %0, %1;" : "=f"(r) : "f"(x));
    return r;
}
__device__ __forceinline__ uint32_t packh2(float a, float b) {
    __half2 h = __floats2half2_rn(a, b);
    return *(uint32_t*)&h;
}
__device__ __forceinline__ void mma_f16(float d[4], const uint32_t a[4],
                                        const uint32_t b[2], const float c[4]) {
    asm volatile(
        "mma.sync.aligned.m16n8k16.row.col.f32.f16.f16.f32 "
        "{%0,%1,%2,%3}, {%4,%5,%6,%7}, {%8,%9}, {%10,%11,%12,%13};\n"
        : "=f"(d[0]), "=f"(d[1]), "=f"(d[2]), "=f"(d[3])
        : "r"(a[0]), "r"(a[1]), "r"(a[2]), "r"(a[3]),
          "r"(b[0]), "r"(b[1]),
          "f"(c[0]), "f"(c[1]), "f"(c[2]), "f"(c[3]));
}
__device__ __forceinline__ void ldsm4(uint32_t& r0, uint32_t& r1,
                                      uint32_t& r2, uint32_t& r3, uint32_t addr) {
    asm volatile("ldmatrix.sync.aligned.m8n8.x4.shared.b16 {%0,%1,%2,%3}, [%4];\n"
                 : "=r"(r0), "=r"(r1), "=r"(r2), "=r"(r3) : "r"(addr));
}

// ---------------------------------------------------------------------------
// Elementwise fp32 -> fp16 rounding
// ---------------------------------------------------------------------------
__global__ __launch_bounds__(256) void round_f16_kernel(
    const float* __restrict__ in, __half* __restrict__ out, int n4)
{
    int i = blockIdx.x * 256 + threadIdx.x;
    if (i < n4) {
        float4 v = ((const float4*)in)[i];
        __half2 lo = __floats2half2_rn(v.x, v.y);
        __half2 hi = __floats2half2_rn(v.z, v.w);
        uint2 u;
        u.x = *(uint32_t*)&lo; u.y = *(uint32_t*)&hi;
        ((uint2*)out)[i] = u;
    }
}

// ---------------------------------------------------------------------------
// FP16 NT GEMM: C = scale*(A[M,K] @ W[N,K]^T) (+ bias), fp32 accumulate.
// Tile 128x64x64, 128 threads = 4 warps x 32 rows; ldmatrix A and B frags.
// OUT_MODE: 0 = fp32, 2 = half, 3 = half scattered V^T [b][h][d][key]
// ---------------------------------------------------------------------------
#define GSTR 72
#define GEMM_SMEM ((2*128*GSTR + 2*64*GSTR) * 2)

template <bool HAS_BIAS, int OUT_MODE>
__global__ __launch_bounds__(128) void gemm_f16_kernel(
    const __half* __restrict__ A, const __half* __restrict__ W,
    const float* __restrict__ bias, void* __restrict__ Cv,
    int M, int N, int K, float scale)
{
    extern __shared__ __half gsh[];
    __half* sA = gsh;                    // [2][128][72]
    __half* sW = gsh + 2*128*GSTR;       // [2][64][72]
    const uint32_t sA_u = smem_u32(sA);
    const uint32_t sW_u = smem_u32(sW);

    const int tid = threadIdx.x;
    const int lane = tid & 31, w = tid >> 5;
    const int g = lane >> 2, t = lane & 3;
    const int bm = blockIdx.y * 128, bn = blockIdx.x * 64;
    const int NIT = K / 64;

    const int arow = (lane & 15), acol = (lane >> 4)*8;
    const int brow = ((lane >> 4)*8 + (lane & 7));
    const int bcol = ((lane >> 3) & 1)*8;

    float acc[2][8][4];
#pragma unroll
    for (int r = 0; r < 2; r++)
#pragma unroll
        for (int nb = 0; nb < 8; nb++)
#pragma unroll
            for (int j = 0; j < 4; j++) acc[r][nb][j] = 0.f;

    {
#pragma unroll
        for (int i = 0; i < 8; i++) {
            int idx = tid + i*128, row = idx >> 3, c = idx & 7;
            cp16(sA_u + (row*GSTR + c*8)*2, A + (size_t)(bm + row)*K + c*8);
        }
#pragma unroll
        for (int i = 0; i < 4; i++) {
            int idx = tid + i*128, row = idx >> 3, c = idx & 7;
            cp16(sW_u + (row*GSTR + c*8)*2, W + (size_t)(bn + row)*K + c*8);
        }
        CP_COMMIT();
    }

    for (int it = 0; it < NIT; it++) {
        const int buf = it & 1;
        if (it + 1 < NIT) {
            const int k0 = (it + 1) * 64, nbuf = buf ^ 1;
#pragma unroll
            for (int i = 0; i < 8; i++) {
                int idx = tid + i*128, row = idx >> 3, c = idx & 7;
                cp16(sA_u + (nbuf*128*GSTR + row*GSTR + c*8)*2,
                     A + (size_t)(bm + row)*K + k0 + c*8);
            }
#pragma unroll
            for (int i = 0; i < 4; i++) {
                int idx = tid + i*128, row = idx >> 3, c = idx & 7;
                cp16(sW_u + (nbuf*64*GSTR + row*GSTR + c*8)*2,
                     W + (size_t)(bn + row)*K + k0 + c*8);
            }
            CP_COMMIT();
            CP_WAIT1();
        } else {
            CP_WAIT0();
        }
        __syncthreads();

        const uint32_t tA_u = sA_u + buf*128*GSTR*2;
        const uint32_t tW_u = sW_u + buf*64*GSTR*2;

#pragma unroll
        for (int ks = 0; ks < 4; ks++) {
            uint32_t a0[4], a1[4];
            ldsm4(a0[0], a0[1], a0[2], a0[3],
                  tA_u + ((w*32 + arow)*GSTR + ks*16 + acol)*2);
            ldsm4(a1[0], a1[1], a1[2], a1[3],
                  tA_u + ((w*32 + 16 + arow)*GSTR + ks*16 + acol)*2);
#pragma unroll
            for (int p = 0; p < 4; p++) {
                uint32_t b0, b1, b2, b3;
                ldsm4(b0, b1, b2, b3,
                      tW_u + ((p*16 + brow)*GSTR + ks*16 + bcol)*2);
                uint32_t bl[2] = {b0, b1}, bh[2] = {b2, b3};
                mma_f16(acc[0][2*p    ], a0, bl, acc[0][2*p    ]);
                mma_f16(acc[0][2*p + 1], a0, bh, acc[0][2*p + 1]);
                mma_f16(acc[1][2*p    ], a1, bl, acc[1][2*p    ]);
                mma_f16(acc[1][2*p + 1], a1, bh, acc[1][2*p + 1]);
            }
        }
        __syncthreads();
    }

#pragma unroll
    for (int r = 0; r < 2; r++) {
        const int r0 = bm + w*32 + r*16 + g, r1 = r0 + 8;
#pragma unroll
        for (int nb = 0; nb < 8; nb++) {
            const int col = bn + nb*8 + 2*t;
            float v00 = acc[r][nb][0]*scale, v01 = acc[r][nb][1]*scale;
            float v10 = acc[r][nb][2]*scale, v11 = acc[r][nb][3]*scale;
            if (HAS_BIAS) {
                float b0 = bias[col], b1 = bias[col + 1];
                v00 += b0; v01 += b1; v10 += b0; v11 += b1;
            }
            if (OUT_MODE == 0) {
                float* C = (float*)Cv;
                *(float2*)&C[(size_t)r0*N + col] = make_float2(v00, v01);
                *(float2*)&C[(size_t)r1*N + col] = make_float2(v10, v11);
            } else if (OUT_MODE == 2) {
                __half* C = (__half*)Cv;
                *(__half2*)&C[(size_t)r0*N + col] = __floats2half2_rn(v00, v01);
                *(__half2*)&C[(size_t)r1*N + col] = __floats2half2_rn(v10, v11);
            } else {
                __half* C = (__half*)Cv;
                int b_ = r0 >> 12;
                int key0 = r0 & (NKV - 1), key1 = r1 & (NKV - 1);
                size_t base0 = ((size_t)(b_*NH + (col >> 6))*HD + (col & 63)) * NKV;
                size_t base1 = base0 + NKV;
                C[base0 + key0] = __float2half_rn(v00);
                C[base1 + key0] = __float2half_rn(v01);
                C[base0 + key1] = __float2half_rn(v10);
                C[base1 + key1] = __float2half_rn(v11);
            }
        }
    }
}

// ---------------------------------------------------------------------------
// Flash-attention core, fp16 + m16n8k16, fp32 accumulate.
// R15 = R14 resubmitted (infra failure, never ran): register-direct P
// (no P smem round trip) at __launch_bounds__(128, 2): 256-reg cap, no
// spills (R13's (128,3) ~170-reg cap forced spills and regressed).
// ---------------------------------------------------------------------------
#define BQ    128
#define KT    64
#define STRH  72
#define NITA  (NKV / KT)
#define ATTN_SMEM ((2*KT*STRH + 2*KT*STRH + BQ*STRH) * 2)

__global__ __launch_bounds__(128, 2) void attn_mma_kernel()
{
    extern __shared__ __half smh[];
    __half* sK  = smh;                   // [2][64][72]
    __half* sVt = sK + 2*KT*STRH;        // [2][64][72]
    __half* sQ  = sVt + 2*KT*STRH;       // [128][72]  Q staging only
    const uint32_t sK_u  = smem_u32(sK);
    const uint32_t sVt_u = smem_u32(sVt);
    const uint32_t sQ_u  = smem_u32(sQ);

    const int qt = blockIdx.x, h = blockIdx.y, b = blockIdx.z;
    const int tid = threadIdx.x, lane = tid & 31, w = tid >> 5;
    const int g = lane >> 2, t = lane & 3;

    const __half* Qb  = g_Qh + (size_t)(b*NQ + qt*BQ)*INNER + h*HD;
    const __half* Kb  = g_Kh + (size_t)b*NKV*INNER + h*HD;
    const __half* Vtb = g_Vh + ((size_t)(b*NH + h)*HD)*NKV;

    const int kvrow = ((lane >> 4)*8 + (lane & 7));
    const int kvcol = ((lane >> 3) & 1)*8;

#pragma unroll
    for (int i = 0; i < 8; i++) {
        int idx = tid + i*128, row = idx >> 3, c = idx & 7;
        cp16(sQ_u + (row*STRH + c*8)*2, Qb + (size_t)row*INNER + c*8);
    }
    CP_COMMIT();

#pragma unroll
    for (int i = 0; i < 4; i++) {
        int idx = tid + i*128, row = idx >> 3, c = idx & 7;
        cp16(sK_u  + (row*STRH + c*8)*2, Kb  + (size_t)row*INNER + c*8);
        cp16(sVt_u + (row*STRH + c*8)*2, Vtb + (size_t)row*NKV   + c*8);
    }
    CP_COMMIT();

    CP_WAIT1();
    __syncthreads();

    uint32_t qa[2][4][4];
#pragma unroll
    for (int r = 0; r < 2; r++)
#pragma unroll
        for (int ks = 0; ks < 4; ks++) {
            const int row = w*32 + r*16;
            const int c0 = ks*16 + 2*t;
            qa[r][ks][0] = *(const uint32_t*)&sQ[(row + g    )*STRH + c0];
            qa[r][ks][1] = *(const uint32_t*)&sQ[(row + g + 8)*STRH + c0];
            qa[r][ks][2] = *(const uint32_t*)&sQ[(row + g    )*STRH + c0 + 8];
            qa[r][ks][3] = *(const uint32_t*)&sQ[(row + g + 8)*STRH + c0 + 8];
        }

    float m0[2], m1[2], l0[2], l1[2];
#pragma unroll
    for (int r = 0; r < 2; r++) { m0[r] = m1[r] = -INFINITY; l0[r] = l1[r] = 0.f; }
    float o[2][8][4];
#pragma unroll
    for (int r = 0; r < 2; r++)
#pragma unroll
        for (int db = 0; db < 8; db++)
#pragma unroll
            for (int j = 0; j < 4; j++) o[r][db][j] = 0.f;

    for (int it = 0; it < NITA; it++) {
        const int buf = it & 1;
        if (it + 1 < NITA) {
            const int nbuf = buf ^ 1;
#pragma unroll
            for (int i = 0; i < 4; i++) {
                int idx = tid + i*128, row = idx >> 3, c = idx & 7;
                cp16(sK_u  + (nbuf*KT*STRH + row*STRH + c*8)*2,
                     Kb  + (size_t)((it + 1)*KT + row)*INNER + c*8);
                cp16(sVt_u + (nbuf*KT*STRH + row*STRH + c*8)*2,
                     Vtb + (size_t)row*NKV + (it + 1)*KT + c*8);
            }
            CP_COMMIT();
            CP_WAIT1();
        } else {
            CP_WAIT0();
        }
        __syncthreads();

        const uint32_t tK_u  = sK_u  + buf*KT*STRH*2;
        const uint32_t tVt_u = sVt_u + buf*KT*STRH*2;

        // ---- S = Q K^T ----
        float s[2][8][4];
#pragma unroll
        for (int r = 0; r < 2; r++)
#pragma unroll
            for (int nb = 0; nb < 8; nb++)
#pragma unroll
                for (int j = 0; j < 4; j++) s[r][nb][j] = 0.f;

#pragma unroll
        for (int ks = 0; ks < 4; ks++) {
#pragma unroll
            for (int p = 0; p < 4; p++) {
                uint32_t b0, b1, b2, b3;
                ldsm4(b0, b1, b2, b3,
                      tK_u + ((p*16 + kvrow)*STRH + ks*16 + kvcol)*2);
                uint32_t bl[2] = {b0, b1}, bh[2] = {b2, b3};
                mma_f16(s[0][2*p    ], qa[0][ks], bl, s[0][2*p    ]);
                mma_f16(s[0][2*p + 1], qa[0][ks], bh, s[0][2*p + 1]);
                mma_f16(s[1][2*p    ], qa[1][ks], bl, s[1][2*p    ]);
                mma_f16(s[1][2*p + 1], qa[1][ks], bh, s[1][2*p + 1]);
            }
        }

        // ---- online softmax (exp2 domain); P packed into registers ----
        uint32_t ph[2][8][2];   // [row-block][key-block][row g / g+8] half2
#pragma unroll
        for (int r = 0; r < 2; r++) {
            float rm0 = -INFINITY, rm1 = -INFINITY;
#pragma unroll
            for (int nb = 0; nb < 8; nb++) {
                rm0 = fmaxf(rm0, fmaxf(s[r][nb][0], s[r][nb][1]));
                rm1 = fmaxf(rm1, fmaxf(s[r][nb][2], s[r][nb][3]));
            }
            rm0 = fmaxf(rm0, __shfl_xor_sync(0xffffffffu, rm0, 1));
            rm0 = fmaxf(rm0, __shfl_xor_sync(0xffffffffu, rm0, 2));
            rm1 = fmaxf(rm1, __shfl_xor_sync(0xffffffffu, rm1, 1));
            rm1 = fmaxf(rm1, __shfl_xor_sync(0xffffffffu, rm1, 2));

            float mn0 = fmaxf(m0[r], rm0), mn1 = fmaxf(m1[r], rm1);
            float corr0 = ex2(m0[r] - mn0), corr1 = ex2(m1[r] - mn1);
            m0[r] = mn0; m1[r] = mn1;

            float rs0 = 0.f, rs1 = 0.f;
#pragma unroll
            for (int nb = 0; nb < 8; nb++) {
                float e0 = ex2(s[r][nb][0] - mn0);
                float e1 = ex2(s[r][nb][1] - mn0);
                float e2 = ex2(s[r][nb][2] - mn1);
                float e3 = ex2(s[r][nb][3] - mn1);
                rs0 += e0 + e1;
                rs1 += e2 + e3;
                ph[r][nb][0] = packh2(e0, e1);
                ph[r][nb][1] = packh2(e2, e3);
            }
            rs0 += __shfl_xor_sync(0xffffffffu, rs0, 1);
            rs0 += __shfl_xor_sync(0xffffffffu, rs0, 2);
            rs1 += __shfl_xor_sync(0xffffffffu, rs1, 1);
            rs1 += __shfl_xor_sync(0xffffffffu, rs1, 2);
            l0[r] = l0[r] * corr0 + rs0;
            l1[r] = l1[r] * corr1 + rs1;

#pragma unroll
            for (int db = 0; db < 8; db++) {
                o[r][db][0] *= corr0; o[r][db][1] *= corr0;
                o[r][db][2] *= corr1; o[r][db][3] *= corr1;
            }
        }

        // ---- O += P V : P fragments direct from registers ----
#pragma unroll
        for (int ks = 0; ks < 4; ks++) {
            uint32_t pa0[4] = { ph[0][2*ks][0], ph[0][2*ks][1],
                                ph[0][2*ks+1][0], ph[0][2*ks+1][1] };
            uint32_t pa1[4] = { ph[1][2*ks][0], ph[1][2*ks][1],
                                ph[1][2*ks+1][0], ph[1][2*ks+1][1] };
#pragma unroll
            for (int p = 0; p < 4; p++) {
                uint32_t b0, b1, b2, b3;
                ldsm4(b0, b1, b2, b3,
                      tVt_u + ((p*16 + kvrow)*STRH + ks*16 + kvcol)*2);
                uint32_t bl[2] = {b0, b1}, bh[2] = {b2, b3};
                mma_f16(o[0][2*p    ], pa0, bl, o[0][2*p    ]);
                mma_f16(o[0][2*p + 1], pa0, bh, o[0][2*p + 1]);
                mma_f16(o[1][2*p    ], pa1, bl, o[1][2*p    ]);
                mma_f16(o[1][2*p + 1], pa1, bh, o[1][2*p + 1]);
            }
        }
        __syncthreads();
    }

    // ---- epilogue ----
#pragma unroll
    for (int r = 0; r < 2; r++) {
        const float inv0 = 1.f / l0[r], inv1 = 1.f / l1[r];
        const int q0 = qt*BQ + w*32 + r*16 + g, q1 = q0 + 8;
#pragma unroll
        for (int db = 0; db < 8; db++) {
            *(__half2*)&g_AOh[(size_t)(b*NQ + q0)*INNER + h*HD + db*8 + 2*t] =
                __floats2half2_rn(o[r][db][0]*inv0, o[r][db][1]*inv0);
            *(__half2*)&g_AOh[(size_t)(b*NQ + q1)*INNER + h*HD + db*8 + 2*t] =
                __floats2half2_rn(o[r][db][2]*inv1, o[r][db][3]*inv1);
        }
    }
}

// ---------------------------------------------------------------------------
// Launch
// ---------------------------------------------------------------------------
extern "C" void kernel_launch(void* const* d_in, const int* in_sizes, int n_in,
                              void* d_out, int out_size)
{
    const float* q   = (const float*)d_in[0];
    const float* kv  = (const float*)d_in[1];
    const float* w_q = (const float*)d_in[2];
    const float* w_k = (const float*)d_in[3];
    const float* w_v = (const float*)d_in[4];
    const float* w_o = (const float*)d_in[5];
    const float* b_o = (const float*)d_in[6];
    float* out = (float*)d_out;

    void *Qh, *Kh, *Vh, *AOh, *Rq, *Rkv, *Rwq, *Rwk, *Rwv, *Rwo;
    cudaGetSymbolAddress(&Qh,  g_Qh);
    cudaGetSymbolAddress(&Kh,  g_Kh);
    cudaGetSymbolAddress(&Vh,  g_Vh);
    cudaGetSymbolAddress(&AOh, g_AOh);
    cudaGetSymbolAddress(&Rq,  g_Rq);
    cudaGetSymbolAddress(&Rkv, g_Rkv);
    cudaGetSymbolAddress(&Rwq, g_Rwq);
    cudaGetSymbolAddress(&Rwk, g_Rwk);
    cudaGetSymbolAddress(&Rwv, g_Rwv);
    cudaGetSymbolAddress(&Rwo, g_Rwo);

    const int MQ = BB * NQ;    // 8192
    const int MK = BB * NKV;   // 16384

    cudaFuncSetAttribute(gemm_f16_kernel<false, 2>,
                         cudaFuncAttributeMaxDynamicSharedMemorySize, GEMM_SMEM);
    cudaFuncSetAttribute(gemm_f16_kernel<false, 3>,
                         cudaFuncAttributeMaxDynamicSharedMemorySize, GEMM_SMEM);
    cudaFuncSetAttribute(gemm_f16_kernel<true, 0>,
                         cudaFuncAttributeMaxDynamicSharedMemorySize, GEMM_SMEM);
    cudaFuncSetAttribute(attn_mma_kernel,
                         cudaFuncAttributeMaxDynamicSharedMemorySize, ATTN_SMEM);

    // ---- pre-round GEMM inputs to fp16 ----
    {
        int n;
        n = MQ*QDIM/4;      round_f16_kernel<<<(n+255)/256, 256>>>(q,   (__half*)Rq,  n);
        n = MK*KVDIM/4;     round_f16_kernel<<<(n+255)/256, 256>>>(kv,  (__half*)Rkv, n);
        n = INNER*QDIM/4;   round_f16_kernel<<<(n+255)/256, 256>>>(w_q, (__half*)Rwq, n);
        n = INNER*KVDIM/4;  round_f16_kernel<<<(n+255)/256, 256>>>(w_k, (__half*)Rwk, n);
        n = INNER*KVDIM/4;  round_f16_kernel<<<(n+255)/256, 256>>>(w_v, (__half*)Rwv, n);
        n = QDIM*INNER/4;   round_f16_kernel<<<(n+255)/256, 256>>>(w_o, (__half*)Rwo, n);
    }

    gemm_f16_kernel<false, 2><<<dim3(INNER/64, MQ/128), 128, GEMM_SMEM>>>(
        (__half*)Rq, (__half*)Rwq, nullptr, Qh, MQ, INNER, QDIM, Q_PRESCALE);
    gemm_f16_kernel<false, 2><<<dim3(INNER/64, MK/128), 128, GEMM_SMEM>>>(
        (__half*)Rkv, (__half*)Rwk, nullptr, Kh, MK, INNER, KVDIM, 1.0f);
    gemm_f16_kernel<false, 3><<<dim3(INNER/64, MK/128), 128, GEMM_SMEM>>>(
        (__half*)Rkv, (__half*)Rwv, nullptr, Vh, MK, INNER, KVDIM, 1.0f);

    attn_mma_kernel<<<dim3(NQ/BQ, NH, BB), 128, ATTN_SMEM>>>();

    gemm_f16_kernel<true, 0><<<dim3(QDIM/64, MQ/128), 128, GEMM_SMEM>>>(
        (__half*)AOh, (__half*)Rwo, b_o, out, MQ, QDIM, INNER, 1.0f);
}